// round 16
// baseline (speedup 1.0000x reference)
#include <cuda_runtime.h>
#include <cuda_fp16.h>
#include <math.h>
#include <stdint.h>

#define BATCH   8192
#define DIM     256
#define KRED    1024
#define NCOEF   5
#define NLAYERS 2
#define LN_EPS  1e-6f

// ---------------------------------------------------------------------------
// Scratch
// ---------------------------------------------------------------------------
__device__ __half g_dm[BATCH * KRED];            // design matrix fp16
__device__ float  g_h [BATCH * DIM];
__device__ __half g_Bn[NLAYERS * DIM * KRED];
__device__ float  g_bias[NLAYERS * DIM];
__device__ float  g_jc[NLAYERS * 8];

// ---------------------------------------------------------------------------
// Helpers
// ---------------------------------------------------------------------------
__device__ __forceinline__ uint32_t smem_u32(const void* p) {
    uint32_t a;
    asm("{ .reg .u64 t; cvta.to.shared.u64 t, %1; cvt.u32.u64 %0, t; }"
        : "=r"(a) : "l"(p));
    return a;
}
__device__ __forceinline__ float tanh_fast(float v) {
    float r;
    asm("tanh.approx.f32 %0, %1;" : "=f"(r) : "f"(v));
    return r;
}
__device__ __forceinline__ void mma_f16_16n8k16(float* d, const uint32_t* a,
                                                const uint32_t* b) {
    asm volatile(
        "mma.sync.aligned.m16n8k16.row.col.f32.f16.f16.f32 "
        "{%0,%1,%2,%3}, {%4,%5,%6,%7}, {%8,%9}, {%0,%1,%2,%3};"
        : "+f"(d[0]), "+f"(d[1]), "+f"(d[2]), "+f"(d[3])
        : "r"(a[0]), "r"(a[1]), "r"(a[2]), "r"(a[3]),
          "r"(b[0]), "r"(b[1]));
}
#define LDSM4(r0, r1, r2, r3, addr) \
    asm volatile("ldmatrix.sync.aligned.m8n8.x4.shared.b16 {%0,%1,%2,%3}, [%4];" \
        : "=r"(r0), "=r"(r1), "=r"(r2), "=r"(r3) : "r"(addr))
#define CP_ASYNC16(dst, src) \
    asm volatile("cp.async.cg.shared.global [%0], [%1], 16;" \
        :: "r"(dst), "l"(src))
#define CP_COMMIT()  asm volatile("cp.async.commit_group;" ::: "memory")
#define CP_WAIT2()   asm volatile("cp.async.wait_group 2;"  ::: "memory")

// ---------------------------------------------------------------------------
// build Bn[l][o][k], k = i*4 + (c-1), fp16
// ---------------------------------------------------------------------------
__global__ void build_Bn(const float* __restrict__ coefs,
                         __half* __restrict__ Bn) {
    int idx = blockIdx.x * blockDim.x + threadIdx.x;
    const int total = NLAYERS * DIM * KRED;
    if (idx >= total) return;
    int k = idx & (KRED - 1);
    int o = (idx >> 10) & (DIM - 1);
    int l = idx >> 18;
    int i = k >> 2;
    int c = (k & 3) + 1;
    Bn[idx] = __float2half_rn(
        coefs[(((size_t)(l * DIM + i)) * DIM + o) * NCOEF + c]);
}

// ---------------------------------------------------------------------------
// bias[l][o] = sum_i coefs[l][i][o][0]; Jacobi coefficient table
// ---------------------------------------------------------------------------
__global__ void __launch_bounds__(128)
build_bias(const float* __restrict__ coefs, const float* __restrict__ alphas,
           float* __restrict__ bias, float* __restrict__ jc) {
    int lo = blockIdx.x;
    int l = lo >> 8, o = lo & 255;
    float s = 0.0f;
    for (int i = threadIdx.x; i < DIM; i += 128)
        s += coefs[(((size_t)(l * DIM + i)) * DIM + o) * NCOEF];
    #pragma unroll
    for (int off = 16; off; off >>= 1) s += __shfl_xor_sync(0xFFFFFFFFu, s, off);
    __shared__ float red[4];
    if ((threadIdx.x & 31) == 0) red[threadIdx.x >> 5] = s;
    __syncthreads();
    if (threadIdx.x == 0)
        bias[lo] = red[0] + red[1] + red[2] + red[3];

    if (o == 0 && threadIdx.x == 0) {
        float a = tanhf(alphas[l]);
        jc[l * 8 + 0] = a + 1.0f;
        #pragma unroll
        for (int k = 2; k <= 4; k++) {
            float kf = (float)k;
            float t  = 2.0f * kf + 2.0f * a;
            float A  = 2.0f * kf * (kf + 2.0f * a) * (t - 2.0f);
            float B  = (t - 1.0f) * t * (t - 2.0f);
            float Cc = 2.0f * (kf + a - 1.0f) * (kf + a - 1.0f) * t;
            jc[l * 8 + (k - 1)]     = B / A;
            jc[l * 8 + 3 + (k - 1)] = Cc / A;
        }
        jc[l * 8 + 7] = 0.0f;
    }
}

// ---------------------------------------------------------------------------
// ln_jacobi: one WARP per row. float4 loads, shuffle stats, fast tanh,
// coalesced 16B fp16 stores. grid = BATCH/8 blocks x 256 thr (8 warps).
// ---------------------------------------------------------------------------
__global__ void __launch_bounds__(256)
ln_jacobi(const float* __restrict__ h,
          const float* __restrict__ lnscale,
          const float* __restrict__ lnbias,
          const float* __restrict__ jc,
          __half* __restrict__ dm) {
    const int lid = threadIdx.x & 31;
    const int row = blockIdx.x * 8 + (threadIdx.x >> 5);

    const float4 j0 = __ldg((const float4*)jc);
    const float4 j1 = __ldg((const float4*)jc + 1);

    const float4* hr = (const float4*)(h + (size_t)row * DIM);
    float4 a = hr[lid * 2];
    float4 b = hr[lid * 2 + 1];

    float s  = a.x + a.y + a.z + a.w + b.x + b.y + b.z + b.w;
    float s2 = a.x*a.x + a.y*a.y + a.z*a.z + a.w*a.w
             + b.x*b.x + b.y*b.y + b.z*b.z + b.w*b.w;
    #pragma unroll
    for (int off = 16; off; off >>= 1) {
        s  += __shfl_xor_sync(0xFFFFFFFFu, s,  off);
        s2 += __shfl_xor_sync(0xFFFFFFFFu, s2, off);
    }
    float mu = s * (1.0f / DIM);
    float rs = rsqrtf(s2 * (1.0f / DIM) - mu * mu + LN_EPS);

    float4 sc0 = *(const float4*)(lnscale + lid * 8);
    float4 sc1 = *(const float4*)(lnscale + lid * 8 + 4);
    float4 bi0 = *(const float4*)(lnbias  + lid * 8);
    float4 bi1 = *(const float4*)(lnbias  + lid * 8 + 4);

    float v[8]  = {a.x, a.y, a.z, a.w, b.x, b.y, b.z, b.w};
    float sc[8] = {sc0.x, sc0.y, sc0.z, sc0.w, sc1.x, sc1.y, sc1.z, sc1.w};
    float bi[8] = {bi0.x, bi0.y, bi0.z, bi0.w, bi1.x, bi1.y, bi1.z, bi1.w};

    uint32_t oh[16];
    #pragma unroll
    for (int j = 0; j < 8; j++) {
        float x  = tanh_fast((v[j] - mu) * rs * sc[j] + bi[j]);
        float P1 = j0.x * x;
        float P2 = j0.y * x * P1 - j1.x;
        float P3 = j0.z * x * P2 - j1.y * P1;
        float P4 = j0.w * x * P3 - j1.z * P2;
        __half2 h0 = __floats2half2_rn(P1, P2);
        __half2 h1 = __floats2half2_rn(P3, P4);
        oh[2 * j]     = *(uint32_t*)&h0;
        oh[2 * j + 1] = *(uint32_t*)&h1;
    }

    uint4* dst = (uint4*)(dm + (size_t)row * KRED + lid * 32);
    #pragma unroll
    for (int q = 0; q < 4; q++)
        dst[q] = make_uint4(oh[4*q], oh[4*q+1], oh[4*q+2], oh[4*q+3]);
}

// ---------------------------------------------------------------------------
// Pure fp16 HMMA GEMM: C = (A @ Bn^T + bias) / DIM
// CTA 64(M) x 128(N), BK=64, 256 thr, 8 warps (2m x 4n, 32x32 warp tiles).
// A and B both via 4-stage cp.async rings; register-double-buffered frags.
// smem 110.6 KB -> 2 CTAs/SM.
// ---------------------------------------------------------------------------
#define BK        64
#define NCHUNK    (KRED / BK)         // 16
#define ROWB      144
#define A_TILE_B  (64 * ROWB)         // 9216
#define B_TILE_B  (128 * ROWB)        // 18432
#define SM_AOFF   0
#define SM_BOFF   (4 * A_TILE_B)      // 36864
#define SMEM_GEMM_BYTES (4 * A_TILE_B + 4 * B_TILE_B)  // 110592

__global__ void __launch_bounds__(256, 2)
gemm64(const __half* __restrict__ A,
       const __half* __restrict__ Bn,
       const float* __restrict__ biasP0,
       float* __restrict__ C) {
    extern __shared__ char sm[];
    const uint32_t sb = smem_u32(sm);

    const int tid = threadIdx.x;
    const int lid = tid & 31;
    const int wid = tid >> 5;
    const int warp_m = wid & 1;
    const int warp_n = wid >> 1;
    const int qr = lid >> 2;
    const int qc = lid & 3;

    const int bm = blockIdx.x * 64;
    const int bn = blockIdx.y * 128;

    // one stage: A 64 rows (512 x 16B tasks) + B 128 rows (1024 x 16B tasks)
    auto issue = [&](int ch) {
        const uint32_t stA = sb + SM_AOFF + (uint32_t)(ch & 3) * A_TILE_B;
        const uint32_t stB = sb + SM_BOFF + (uint32_t)(ch & 3) * B_TILE_B;
        #pragma unroll
        for (int it = 0; it < 2; it++) {
            int idx = tid + it * 256;
            int row = idx >> 3, q8 = idx & 7;
            const __half* ga = A + (size_t)(bm + row) * KRED + ch * BK + q8 * 8;
            CP_ASYNC16(stA + row * ROWB + q8 * 16, ga);
        }
        #pragma unroll
        for (int it = 0; it < 4; it++) {
            int idx = tid + it * 256;
            int row = idx >> 3, q8 = idx & 7;
            const __half* gb = Bn + (size_t)(bn + row) * KRED + ch * BK + q8 * 8;
            CP_ASYNC16(stB + row * ROWB + q8 * 16, gb);
        }
        CP_COMMIT();
    };

    issue(0); issue(1); issue(2);

    const uint32_t a_loff =
        (uint32_t)((warp_m * 32 + (lid & 15)) * ROWB + ((lid >> 4) << 4));
    const uint32_t b_loff =
        (uint32_t)((warp_n * 32 + ((lid & 7) | ((lid >> 4) << 3))) * ROWB +
                   (((lid >> 3) & 1) << 4));

    float acc[2][4][4];
    #pragma unroll
    for (int mt = 0; mt < 2; mt++)
        #pragma unroll
        for (int nt = 0; nt < 4; nt++)
            #pragma unroll
            for (int j = 0; j < 4; j++) acc[mt][nt][j] = 0.0f;

    CP_WAIT2();
    __syncthreads();

    uint32_t af[2][2][4], bf[2][4][2];

    #pragma unroll 1
    for (int c = 0; c < NCHUNK; c++) {
        const uint32_t stA = sb + SM_AOFF + (uint32_t)(c & 3) * A_TILE_B;
        const uint32_t stB = sb + SM_BOFF + (uint32_t)(c & 3) * B_TILE_B;

        // preload ks=0 fragments
        #pragma unroll
        for (int mt = 0; mt < 2; mt++)
            LDSM4(af[0][mt][0], af[0][mt][1], af[0][mt][2], af[0][mt][3],
                  stA + a_loff + (uint32_t)(mt * 16 * ROWB));
        #pragma unroll
        for (int p = 0; p < 2; p++)
            LDSM4(bf[0][2*p][0], bf[0][2*p][1], bf[0][2*p+1][0], bf[0][2*p+1][1],
                  stB + b_loff + (uint32_t)(p * 16 * ROWB));

        if (c + 3 < NCHUNK) issue(c + 3);
        else CP_COMMIT();

        #pragma unroll
        for (int ks = 0; ks < 4; ks++) {
            const int cur = ks & 1;
            if (ks < 3) {
                const int nxt = cur ^ 1;
                #pragma unroll
                for (int mt = 0; mt < 2; mt++)
                    LDSM4(af[nxt][mt][0], af[nxt][mt][1],
                          af[nxt][mt][2], af[nxt][mt][3],
                          stA + a_loff + (uint32_t)(mt * 16 * ROWB + (ks + 1) * 32));
                #pragma unroll
                for (int p = 0; p < 2; p++)
                    LDSM4(bf[nxt][2*p][0], bf[nxt][2*p][1],
                          bf[nxt][2*p+1][0], bf[nxt][2*p+1][1],
                          stB + b_loff + (uint32_t)(p * 16 * ROWB + (ks + 1) * 32));
            }
            #pragma unroll
            for (int mt = 0; mt < 2; mt++)
                #pragma unroll
                for (int nt = 0; nt < 4; nt++)
                    mma_f16_16n8k16(acc[mt][nt], af[cur][mt], bf[cur][nt]);
        }

        if (c + 1 < NCHUNK) {
            CP_WAIT2();
            __syncthreads();
        }
    }

    const float inv = 1.0f / (float)DIM;
    const int re = bm + warp_m * 32 + qr;
    const int ce = bn + warp_n * 32 + qc * 2;
    #pragma unroll
    for (int mt = 0; mt < 2; mt++) {
        #pragma unroll
        for (int nt = 0; nt < 4; nt++) {
            int col = ce + nt * 8;
            float2 bv = *(const float2*)(biasP0 + col);
            int row = re + mt * 16;
            float2 o0, o1;
            o0.x = (acc[mt][nt][0] + bv.x) * inv;
            o0.y = (acc[mt][nt][1] + bv.y) * inv;
            o1.x = (acc[mt][nt][2] + bv.x) * inv;
            o1.y = (acc[mt][nt][3] + bv.y) * inv;
            *(float2*)(C + (size_t)row * DIM + col)       = o0;
            *(float2*)(C + (size_t)(row + 8) * DIM + col) = o1;
        }
    }
}

// ---------------------------------------------------------------------------
// Launch
// ---------------------------------------------------------------------------
extern "C" void kernel_launch(void* const* d_in, const int* in_sizes, int n_in,
                              void* d_out, int out_size) {
    const float* x        = (const float*)d_in[0];
    const float* coefs    = (const float*)d_in[1];
    const float* alphas   = (const float*)d_in[2];
    const float* ln_scale = (const float*)d_in[3];
    const float* ln_bias  = (const float*)d_in[4];
    float* out = (float*)d_out;

    __half* dm;  cudaGetSymbolAddress((void**)&dm,   g_dm);
    float* hbuf; cudaGetSymbolAddress((void**)&hbuf, g_h);
    __half* Bn;  cudaGetSymbolAddress((void**)&Bn,   g_Bn);
    float* bias; cudaGetSymbolAddress((void**)&bias, g_bias);
    float* jc;   cudaGetSymbolAddress((void**)&jc,   g_jc);

    cudaFuncSetAttribute(gemm64, cudaFuncAttributeMaxDynamicSharedMemorySize,
                         SMEM_GEMM_BYTES);

    {
        int total = NLAYERS * DIM * KRED;
        build_Bn<<<(total + 255) / 256, 256>>>(coefs, Bn);
        build_bias<<<NLAYERS * DIM, 128>>>(coefs, alphas, bias, jc);
    }

    dim3 ggrid(BATCH / 64, DIM / 128);   // (128, 2) = 256 CTAs

    // Layer 0
    ln_jacobi<<<BATCH / 8, 256>>>(x, ln_scale, ln_bias, jc, dm);
    gemm64<<<ggrid, 256, SMEM_GEMM_BYTES>>>(dm, Bn, bias, hbuf);

    // Layer 1
    ln_jacobi<<<BATCH / 8, 256>>>(hbuf, ln_scale + DIM, ln_bias + DIM, jc + 8, dm);
    gemm64<<<ggrid, 256, SMEM_GEMM_BYTES>>>(dm, Bn + (size_t)DIM * KRED,
                                            bias + DIM, out);
}